// round 4
// baseline (speedup 1.0000x reference)
#include <cuda_runtime.h>

// IntDVF: scaling-and-squaring integration of a stationary velocity field.
//   ddf = dvf / 2^7;  repeat 7x: ddf = ddf + warp(ddf, ddf)
// Shapes: (B=2, 128,128,128, 3) float32, trilinear with clamped indices.
//
// R3 change: process the two batches SEQUENTIALLY through shared 33.5 MB
// ping-pong buffers so each step's src+dst (67 MB) fits in the 126 MB L2.
// R2 measured 98 MB/step of DRAM traffic from the 134 MB working set
// thrashing L2; this eliminates it. Loads stay float4 (one LDG.128/corner).

#define DDIM 128
#define DN   (DDIM * DDIM * DDIM)   // 2097152 voxels per batch
#define NTHREADS 256
#define NBLOCKS (DN / NTHREADS)     // 8192

__device__ float4 g_bufA[DN];
__device__ float4 g_bufB[DN];

// dvf batch slice (AoS float3) -> padded float4, scaled by 1/2^NUM_STEPS
__global__ __launch_bounds__(NTHREADS) void k_scale_pad(const float* __restrict__ in) {
    const float S = 1.0f / 128.0f;  // 2^-7
    int t = blockIdx.x * NTHREADS + threadIdx.x;       // t < DN always
    const float* p = in + (size_t)t * 3;
    g_bufA[t] = make_float4(p[0] * S, p[1] * S, p[2] * S, 0.0f);
}

// One integration step on one batch: dst = src + trilinear(src, grid + src).
// SRC_IS_A selects ping-pong direction; PACK writes float3 to gmem out.
template <bool SRC_IS_A, bool PACK>
__global__ __launch_bounds__(NTHREADS) void k_step(float* __restrict__ out3) {
    const float4* __restrict__ base = SRC_IS_A ? g_bufA : g_bufB;
    float4* __restrict__ dstg       = SRC_IS_A ? g_bufB : g_bufA;

    int t = blockIdx.x * NTHREADS + threadIdx.x;       // t < DN always
    int z = t & 127;
    int y = (t >> 7) & 127;
    int x = t >> 14;

    float4 d = base[t];

    float lx = (float)x + d.x;
    float ly = (float)y + d.y;
    float lz = (float)z + d.z;

    float fx = floorf(lx), fy = floorf(ly), fz = floorf(lz);
    float wx1 = lx - fx, wy1 = ly - fy, wz1 = lz - fz;
    float wx0 = 1.0f - wx1, wy0 = 1.0f - wy1, wz0 = 1.0f - wz1;

    int jx = (int)fx, jy = (int)fy, jz = (int)fz;
    int ix0 = min(max(jx, 0), 127);
    int ix1 = min(max(jx + 1, 0), 127);
    int iy0 = min(max(jy, 0), 127);
    int iy1 = min(max(jy + 1, 0), 127);
    int iz0 = min(max(jz, 0), 127);
    int iz1 = min(max(jz + 1, 0), 127);

    int X0 = ix0 << 14, X1 = ix1 << 14;
    int Y0 = iy0 << 7,  Y1 = iy1 << 7;

    // 8 corner fetches (each one LDG.128) — issue all before consuming for MLP.
    float4 c000 = base[X0 + Y0 + iz0];
    float4 c001 = base[X0 + Y0 + iz1];
    float4 c010 = base[X0 + Y1 + iz0];
    float4 c011 = base[X0 + Y1 + iz1];
    float4 c100 = base[X1 + Y0 + iz0];
    float4 c101 = base[X1 + Y0 + iz1];
    float4 c110 = base[X1 + Y1 + iz0];
    float4 c111 = base[X1 + Y1 + iz1];

    float w00 = wx0 * wy0;
    float w01 = wx0 * wy1;
    float w10 = wx1 * wy0;
    float w11 = wx1 * wy1;

    float w000 = w00 * wz0, w001 = w00 * wz1;
    float w010 = w01 * wz0, w011 = w01 * wz1;
    float w100 = w10 * wz0, w101 = w10 * wz1;
    float w110 = w11 * wz0, w111 = w11 * wz1;

    float ax = d.x, ay = d.y, az = d.z;
    ax = fmaf(w000, c000.x, ax); ay = fmaf(w000, c000.y, ay); az = fmaf(w000, c000.z, az);
    ax = fmaf(w001, c001.x, ax); ay = fmaf(w001, c001.y, ay); az = fmaf(w001, c001.z, az);
    ax = fmaf(w010, c010.x, ax); ay = fmaf(w010, c010.y, ay); az = fmaf(w010, c010.z, az);
    ax = fmaf(w011, c011.x, ax); ay = fmaf(w011, c011.y, ay); az = fmaf(w011, c011.z, az);
    ax = fmaf(w100, c100.x, ax); ay = fmaf(w100, c100.y, ay); az = fmaf(w100, c100.z, az);
    ax = fmaf(w101, c101.x, ax); ay = fmaf(w101, c101.y, ay); az = fmaf(w101, c101.z, az);
    ax = fmaf(w110, c110.x, ax); ay = fmaf(w110, c110.y, ay); az = fmaf(w110, c110.z, az);
    ax = fmaf(w111, c111.x, ax); ay = fmaf(w111, c111.y, ay); az = fmaf(w111, c111.z, az);

    if (PACK) {
        float* q = out3 + (size_t)t * 3;
        q[0] = ax; q[1] = ay; q[2] = az;
    } else {
        dstg[t] = make_float4(ax, ay, az, 0.0f);
    }
}

extern "C" void kernel_launch(void* const* d_in, const int* in_sizes, int n_in,
                              void* d_out, int out_size) {
    const float* dvf = (const float*)d_in[0];
    float* out = (float*)d_out;

    for (int b = 0; b < 2; b++) {
        const float* src = dvf + (size_t)b * DN * 3;
        float* dst       = out + (size_t)b * DN * 3;

        // ddf0 = dvf / 128, padded into A
        k_scale_pad<<<NBLOCKS, NTHREADS>>>(src);

        // 7 squaring steps, ping-pong A<->B; final step un-pads into d_out.
        k_step<true,  false><<<NBLOCKS, NTHREADS>>>(nullptr);  // A -> B  (1)
        k_step<false, false><<<NBLOCKS, NTHREADS>>>(nullptr);  // B -> A  (2)
        k_step<true,  false><<<NBLOCKS, NTHREADS>>>(nullptr);  // A -> B  (3)
        k_step<false, false><<<NBLOCKS, NTHREADS>>>(nullptr);  // B -> A  (4)
        k_step<true,  false><<<NBLOCKS, NTHREADS>>>(nullptr);  // A -> B  (5)
        k_step<false, false><<<NBLOCKS, NTHREADS>>>(nullptr);  // B -> A  (6)
        k_step<true,  true ><<<NBLOCKS, NTHREADS>>>(dst);      // A -> out(7)
    }
}

// round 5
// speedup vs baseline: 1.8217x; 1.8217x over previous
#include <cuda_runtime.h>
#include <cuda_fp16.h>

// IntDVF: scaling-and-squaring integration of a stationary velocity field.
//   ddf = dvf / 2^7;  repeat 7x: ddf = ddf + warp(ddf, ddf)
// Shapes: (B=2, 128,128,128, 3) float32, trilinear with clamped indices.
//
// R5: back to the R2 combined-batch structure (empirically 1.65x better
// per-voxel than batch-split). New: kernel is L1 SECTOR-bandwidth bound,
// so gathers now read a packed half4 (8B) SHADOW of the field -> ~2x fewer
// 32B sectors per gather. The fp32 float4 ping-pong remains the accumulator
// (self-read + store fp32), so only the interpolated increment is fp16-
// quantized: expected rel_err ~2e-4 << 1e-3.

#define DDIM 128
#define DN   (DDIM * DDIM * DDIM)   // 2097152 voxels per batch
#define NBATCH 2
#define NVOX (NBATCH * DN)          // 4194304
#define NTHREADS 256
#define NBLOCKS (NVOX / NTHREADS)   // 16384

struct alignas(8) H4 { __half2 xy; __half2 zw; };

__device__ float4 g_bufA[NVOX];
__device__ float4 g_bufB[NVOX];
__device__ H4     g_hA[NVOX];
__device__ H4     g_hB[NVOX];

__device__ __forceinline__ H4 pack_h4(float x, float y, float z) {
    H4 h;
    h.xy = __floats2half2_rn(x, y);
    h.zw = __floats2half2_rn(z, 0.0f);
    return h;
}

// dvf (AoS float3) -> scaled fp32 float4 + fp16 shadow
__global__ __launch_bounds__(NTHREADS) void k_scale_pad(const float* __restrict__ in) {
    const float S = 1.0f / 128.0f;  // 2^-7
    int t = blockIdx.x * NTHREADS + threadIdx.x;       // t < NVOX always
    const float* p = in + (size_t)t * 3;
    float x = p[0] * S, y = p[1] * S, z = p[2] * S;
    g_bufA[t] = make_float4(x, y, z, 0.0f);
    g_hA[t] = pack_h4(x, y, z);
}

// One step: dst = src + trilinear(src_shadow, grid + src).
template <bool SRC_IS_A, bool PACK>
__global__ __launch_bounds__(NTHREADS) void k_step(float* __restrict__ out3) {
    const float4* __restrict__ base  = SRC_IS_A ? g_bufA : g_bufB;
    const H4*     __restrict__ hbase = SRC_IS_A ? g_hA   : g_hB;
    float4*       __restrict__ dstg  = SRC_IS_A ? g_bufB : g_bufA;
    H4*           __restrict__ hdstg = SRC_IS_A ? g_hB   : g_hA;

    int t = blockIdx.x * NTHREADS + threadIdx.x;       // t < NVOX always
    int b = t >> 21;                                   // DN = 2^21
    int v = t & (DN - 1);
    int z = v & 127;
    int y = (v >> 7) & 127;
    int x = v >> 14;

    const float4* __restrict__ fb = base  + (size_t)b * DN;
    const H4*     __restrict__ hb = hbase + (size_t)b * DN;

    float4 d = fb[v];

    float lx = (float)x + d.x;
    float ly = (float)y + d.y;
    float lz = (float)z + d.z;

    float fx = floorf(lx), fy = floorf(ly), fz = floorf(lz);
    float wx1 = lx - fx, wy1 = ly - fy, wz1 = lz - fz;
    float wx0 = 1.0f - wx1, wy0 = 1.0f - wy1, wz0 = 1.0f - wz1;

    int jx = (int)fx, jy = (int)fy, jz = (int)fz;
    int ix0 = min(max(jx, 0), 127);
    int ix1 = min(max(jx + 1, 0), 127);
    int iy0 = min(max(jy, 0), 127);
    int iy1 = min(max(jy + 1, 0), 127);
    int iz0 = min(max(jz, 0), 127);
    int iz1 = min(max(jz + 1, 0), 127);

    int X0 = ix0 << 14, X1 = ix1 << 14;
    int Y0 = iy0 << 7,  Y1 = iy1 << 7;

    // 8 corner fetches from the fp16 shadow (one LDG.64 each).
    H4 c000 = hb[X0 + Y0 + iz0];
    H4 c001 = hb[X0 + Y0 + iz1];
    H4 c010 = hb[X0 + Y1 + iz0];
    H4 c011 = hb[X0 + Y1 + iz1];
    H4 c100 = hb[X1 + Y0 + iz0];
    H4 c101 = hb[X1 + Y0 + iz1];
    H4 c110 = hb[X1 + Y1 + iz0];
    H4 c111 = hb[X1 + Y1 + iz1];

    float w00 = wx0 * wy0;
    float w01 = wx0 * wy1;
    float w10 = wx1 * wy0;
    float w11 = wx1 * wy1;

    float w000 = w00 * wz0, w001 = w00 * wz1;
    float w010 = w01 * wz0, w011 = w01 * wz1;
    float w100 = w10 * wz0, w101 = w10 * wz1;
    float w110 = w11 * wz0, w111 = w11 * wz1;

    float ax = d.x, ay = d.y, az = d.z;
    #define ACC(W, C) do {                                   \
        float2 _xy = __half22float2((C).xy);                 \
        float  _z  = __half2float(__low2half((C).zw));       \
        ax = fmaf((W), _xy.x, ax);                           \
        ay = fmaf((W), _xy.y, ay);                           \
        az = fmaf((W), _z,    az);                           \
    } while (0)

    ACC(w000, c000); ACC(w001, c001);
    ACC(w010, c010); ACC(w011, c011);
    ACC(w100, c100); ACC(w101, c101);
    ACC(w110, c110); ACC(w111, c111);
    #undef ACC

    if (PACK) {
        float* q = out3 + (size_t)t * 3;
        q[0] = ax; q[1] = ay; q[2] = az;
    } else {
        dstg[t]  = make_float4(ax, ay, az, 0.0f);
        hdstg[t] = pack_h4(ax, ay, az);
    }
}

extern "C" void kernel_launch(void* const* d_in, const int* in_sizes, int n_in,
                              void* d_out, int out_size) {
    const float* dvf = (const float*)d_in[0];
    float* out = (float*)d_out;

    // ddf0 = dvf / 128 into fp32 A + fp16 shadow
    k_scale_pad<<<NBLOCKS, NTHREADS>>>(dvf);

    // 7 squaring steps, ping-pong A<->B; final step writes float3 to d_out.
    k_step<true,  false><<<NBLOCKS, NTHREADS>>>(nullptr);  // A -> B  (1)
    k_step<false, false><<<NBLOCKS, NTHREADS>>>(nullptr);  // B -> A  (2)
    k_step<true,  false><<<NBLOCKS, NTHREADS>>>(nullptr);  // A -> B  (3)
    k_step<false, false><<<NBLOCKS, NTHREADS>>>(nullptr);  // B -> A  (4)
    k_step<true,  false><<<NBLOCKS, NTHREADS>>>(nullptr);  // A -> B  (5)
    k_step<false, false><<<NBLOCKS, NTHREADS>>>(nullptr);  // B -> A  (6)
    k_step<true,  true ><<<NBLOCKS, NTHREADS>>>(out);      // A -> out(7)
}

// round 6
// speedup vs baseline: 2.2822x; 1.2528x over previous
#include <cuda_runtime.h>
#include <cuda_fp16.h>

// IntDVF: scaling-and-squaring integration of a stationary velocity field.
//   ddf = dvf / 2^7;  repeat 7x: ddf = ddf + warp(ddf, ddf)
// Shapes: (B=2, 128,128,128, 3) float32, trilinear with clamped indices.
//
// R6: drop the fp32 float4 ping-pong entirely. The field is carried as
//   hi  = half4 (8B/vox)  -- gather shadow AND self-read high part
//   lo  = 3 planar halves (6B/vox) -- fp16 residual (v - hi)
// v = hi + lo reconstructs ~22-bit relative precision, so accuracy matches
// the fp32 carry (rel_err ~2.2e-4 from hi-only gathers, as R5).
// Working set = 2*(33.5+25.2) = 117 MB -> fits 126 MB L2 -> DRAM ~0.
// Per-step traffic 159 MB -> 118 MB, and the DRAM stall regime disappears.

#define DDIM 128
#define DN   (DDIM * DDIM * DDIM)   // 2097152 voxels per batch
#define NBATCH 2
#define NVOX (NBATCH * DN)          // 4194304
#define NTHREADS 256
#define NBLOCKS (NVOX / NTHREADS)   // 16384

struct alignas(8) H4 { __half2 xy; __half2 zw; };

__device__ H4     g_hA[NVOX];
__device__ H4     g_hB[NVOX];
__device__ __half g_loA[3 * NVOX];   // planes: x @0, y @NVOX, z @2*NVOX
__device__ __half g_loB[3 * NVOX];

__device__ __forceinline__ H4 pack_h4(float x, float y, float z) {
    H4 h;
    h.xy = __floats2half2_rn(x, y);
    h.zw = __floats2half2_rn(z, 0.0f);
    return h;
}

// Split v into hi (already packed) residual lo
__device__ __forceinline__ void store_split(H4* hp, __half* lop, int t,
                                            float x, float y, float z) {
    H4 h = pack_h4(x, y, z);
    hp[t] = h;
    float2 hxy = __half22float2(h.xy);
    float  hz  = __half2float(__low2half(h.zw));
    lop[t]            = __float2half_rn(x - hxy.x);
    lop[t + NVOX]     = __float2half_rn(y - hxy.y);
    lop[t + 2 * NVOX] = __float2half_rn(z - hz);
}

// dvf (AoS float3) -> scaled hi/lo split
__global__ __launch_bounds__(NTHREADS) void k_scale_pad(const float* __restrict__ in) {
    const float S = 1.0f / 128.0f;  // 2^-7
    int t = blockIdx.x * NTHREADS + threadIdx.x;       // t < NVOX always
    const float* p = in + (size_t)t * 3;
    store_split(g_hA, g_loA, t, p[0] * S, p[1] * S, p[2] * S);
}

// One step: dst = src + trilinear(src_hi, grid + src).
template <bool SRC_IS_A, bool PACK>
__global__ __launch_bounds__(NTHREADS) void k_step(float* __restrict__ out3) {
    const H4*     __restrict__ hsrc  = SRC_IS_A ? g_hA  : g_hB;
    const __half* __restrict__ losrc = SRC_IS_A ? g_loA : g_loB;
    H4*           __restrict__ hdst  = SRC_IS_A ? g_hB  : g_hA;
    __half*       __restrict__ lodst = SRC_IS_A ? g_loB : g_loA;

    int t = blockIdx.x * NTHREADS + threadIdx.x;       // t < NVOX always
    int b = t >> 21;                                   // DN = 2^21
    int v = t & (DN - 1);
    int z = v & 127;
    int y = (v >> 7) & 127;
    int x = v >> 14;

    const H4* __restrict__ hb = hsrc + (size_t)b * DN;

    // Self-read: reconstruct fp32 carry = hi + lo
    H4 hself = hsrc[t];
    float2 hxy = __half22float2(hself.xy);
    float  hz  = __half2float(__low2half(hself.zw));
    float dx = hxy.x + __half2float(losrc[t]);
    float dy = hxy.y + __half2float(losrc[t + NVOX]);
    float dz = hz    + __half2float(losrc[t + 2 * NVOX]);

    float lx = (float)x + dx;
    float ly = (float)y + dy;
    float lz = (float)z + dz;

    float fx = floorf(lx), fy = floorf(ly), fz = floorf(lz);
    float wx1 = lx - fx, wy1 = ly - fy, wz1 = lz - fz;
    float wx0 = 1.0f - wx1, wy0 = 1.0f - wy1, wz0 = 1.0f - wz1;

    int jx = (int)fx, jy = (int)fy, jz = (int)fz;
    int ix0 = min(max(jx, 0), 127);
    int ix1 = min(max(jx + 1, 0), 127);
    int iy0 = min(max(jy, 0), 127);
    int iy1 = min(max(jy + 1, 0), 127);
    int iz0 = min(max(jz, 0), 127);
    int iz1 = min(max(jz + 1, 0), 127);

    int X0 = ix0 << 14, X1 = ix1 << 14;
    int Y0 = iy0 << 7,  Y1 = iy1 << 7;

    // 8 corner fetches from the fp16 hi field (one LDG.64 each).
    H4 c000 = hb[X0 + Y0 + iz0];
    H4 c001 = hb[X0 + Y0 + iz1];
    H4 c010 = hb[X0 + Y1 + iz0];
    H4 c011 = hb[X0 + Y1 + iz1];
    H4 c100 = hb[X1 + Y0 + iz0];
    H4 c101 = hb[X1 + Y0 + iz1];
    H4 c110 = hb[X1 + Y1 + iz0];
    H4 c111 = hb[X1 + Y1 + iz1];

    float w00 = wx0 * wy0;
    float w01 = wx0 * wy1;
    float w10 = wx1 * wy0;
    float w11 = wx1 * wy1;

    float w000 = w00 * wz0, w001 = w00 * wz1;
    float w010 = w01 * wz0, w011 = w01 * wz1;
    float w100 = w10 * wz0, w101 = w10 * wz1;
    float w110 = w11 * wz0, w111 = w11 * wz1;

    float ax = dx, ay = dy, az = dz;
    #define ACC(W, C) do {                                   \
        float2 _xy = __half22float2((C).xy);                 \
        float  _z  = __half2float(__low2half((C).zw));       \
        ax = fmaf((W), _xy.x, ax);                           \
        ay = fmaf((W), _xy.y, ay);                           \
        az = fmaf((W), _z,    az);                           \
    } while (0)

    ACC(w000, c000); ACC(w001, c001);
    ACC(w010, c010); ACC(w011, c011);
    ACC(w100, c100); ACC(w101, c101);
    ACC(w110, c110); ACC(w111, c111);
    #undef ACC

    if (PACK) {
        float* q = out3 + (size_t)t * 3;
        q[0] = ax; q[1] = ay; q[2] = az;
    } else {
        store_split(hdst, lodst, t, ax, ay, az);
    }
}

extern "C" void kernel_launch(void* const* d_in, const int* in_sizes, int n_in,
                              void* d_out, int out_size) {
    const float* dvf = (const float*)d_in[0];
    float* out = (float*)d_out;

    // ddf0 = dvf / 128 into hi/lo split A
    k_scale_pad<<<NBLOCKS, NTHREADS>>>(dvf);

    // 7 squaring steps, ping-pong A<->B; final step writes float3 to d_out.
    k_step<true,  false><<<NBLOCKS, NTHREADS>>>(nullptr);  // A -> B  (1)
    k_step<false, false><<<NBLOCKS, NTHREADS>>>(nullptr);  // B -> A  (2)
    k_step<true,  false><<<NBLOCKS, NTHREADS>>>(nullptr);  // A -> B  (3)
    k_step<false, false><<<NBLOCKS, NTHREADS>>>(nullptr);  // B -> A  (4)
    k_step<true,  false><<<NBLOCKS, NTHREADS>>>(nullptr);  // A -> B  (5)
    k_step<false, false><<<NBLOCKS, NTHREADS>>>(nullptr);  // B -> A  (6)
    k_step<true,  true ><<<NBLOCKS, NTHREADS>>>(out);      // A -> out(7)
}